// round 2
// baseline (speedup 1.0000x reference)
#include <cuda_runtime.h>
#include <cuda_bf16.h>

// LNN Euler-Lagrange residual. The MLP is ReLU (piecewise linear), so the
// second-derivative term vanishes under autodiff and the output is exactly
// -dL/dq: one forward (ReLU masks + layer-2 sign) + one backward.
//
// Structure rule enforced everywhere: register arrays (h, d2, o) are indexed
// ONLY by fully-unrolled compile-time-constant loops; runtime loop indices
// touch only shared/global POINTERS. This keeps everything in registers
// (no local-memory demotion, which killed round 0).

#define HID 64

// smem layout (floats):
//   sW1   [64*64] @ 0      row i = W1[i,:]        (layer-1 forward)
//   sW2T  [64*64] @ 4096   row j = W2[:,j]        (layer-2 sign pass)
//   sW2   [64*64] @ 8192   row k = W2[k,:]        (backward dot with d2)
//   sW1T  [64*32] @ 12288  row k = W1[0:32, k]    (backward into q-outputs)
//   sb1   [64]    @ 14336
//   sb2   [64]    @ 14400
//   sW3   [64]    @ 14464
#define SMEM_FLOATS 14528

extern __shared__ float smem[];

__global__ void __launch_bounds__(128)
lnn_kernel(const float* __restrict__ X,
           const float* __restrict__ W1g, const float* __restrict__ b1g,
           const float* __restrict__ W2g, const float* __restrict__ b2g,
           const float* __restrict__ W3g,
           float* __restrict__ out, int B)
{
    float* sW1  = smem;
    float* sW2T = smem + 4096;
    float* sW2  = smem + 8192;
    float* sW1T = smem + 12288;
    float* sb1  = smem + 14336;
    float* sb2  = smem + 14400;
    float* sW3  = smem + 14464;

    const int t = threadIdx.x;

    // ---- cooperative weight staging (one-time per block) ----
    for (int i = t; i < 4096; i += 128) {
        const int r = i >> 6;        // row of W (input / layer-1 hidden dim)
        const int c = i & 63;        // col of W (hidden dim)
        const float w1 = W1g[i];
        const float w2 = W2g[i];
        sW1[i] = w1;
        sW2[i] = w2;
        sW2T[c * 64 + r] = w2;       // row c of W2T = W2[:,c]
        if (r < 32) sW1T[c * 32 + r] = w1;   // row c of W1T = W1[0:32, c]
    }
    if (t < 64) {
        sb1[t] = b1g[t];
        sb2[t] = b2g[t];
        sW3[t] = W3g[t];
    }
    __syncthreads();

    const int s = blockIdx.x * 128 + t;
    if (s >= B) return;

    // =========== layer 1: h = relu(x @ W1 + b1), x streamed from global ====
    float h[HID];
    #pragma unroll
    for (int j = 0; j < HID; j++) h[j] = sb1[j];

    const float4* xg = reinterpret_cast<const float4*>(X + (size_t)s * HID);

    #define L1_ACC(XI, ROWP)                                        \
        do {                                                        \
            const float4* _w = reinterpret_cast<const float4*>(ROWP);\
            _Pragma("unroll")                                       \
            for (int j4 = 0; j4 < 16; j4++) {                       \
                float4 w = _w[j4];                                  \
                h[4*j4+0] = fmaf((XI), w.x, h[4*j4+0]);             \
                h[4*j4+1] = fmaf((XI), w.y, h[4*j4+1]);             \
                h[4*j4+2] = fmaf((XI), w.z, h[4*j4+2]);             \
                h[4*j4+3] = fmaf((XI), w.w, h[4*j4+3]);             \
            }                                                       \
        } while (0)

    #pragma unroll 2
    for (int i4 = 0; i4 < 16; i4++) {
        const float4 xv = xg[i4];
        const float* row = sW1 + (i4 * 4) * 64;
        L1_ACC(xv.x, row);
        L1_ACC(xv.y, row + 64);
        L1_ACC(xv.z, row + 128);
        L1_ACC(xv.w, row + 192);
    }

    // relu + compress layer-1 mask into u64
    unsigned m1lo = 0u, m1hi = 0u;
    #pragma unroll
    for (int j = 0; j < 32; j++) {
        h[j] = fmaxf(h[j], 0.0f);
        if (h[j] > 0.0f) m1lo |= (1u << j);
    }
    #pragma unroll
    for (int j = 0; j < 32; j++) {
        h[32+j] = fmaxf(h[32+j], 0.0f);
        if (h[32+j] > 0.0f) m1hi |= (1u << j);
    }

    // =========== layer 2: only sign(h @ W2 + b2) is needed =================
    unsigned long long m2 = 0ull;
    #pragma unroll 2
    for (int j = 0; j < HID; j++) {
        const float4* wp = reinterpret_cast<const float4*>(sW2T + j * 64);
        float s0 = 0.f, s1 = 0.f, s2 = 0.f, s3 = 0.f;
        #pragma unroll
        for (int j4 = 0; j4 < 16; j4++) {
            float4 w = wp[j4];
            s0 = fmaf(w.x, h[4*j4+0], s0);
            s1 = fmaf(w.y, h[4*j4+1], s1);
            s2 = fmaf(w.z, h[4*j4+2], s2);
            s3 = fmaf(w.w, h[4*j4+3], s3);
        }
        const float gj = ((s0 + s1) + (s2 + s3)) + sb2[j];
        m2 |= (unsigned long long)(gj > 0.0f ? 1u : 0u) << j;
    }

    // d2 = mask2 ? W3 : 0  (h is dead; allocator reuses its registers)
    float d2[HID];
    #pragma unroll
    for (int j = 0; j < HID; j++)
        d2[j] = ((m2 >> j) & 1ull) ? sW3[j] : 0.0f;

    const unsigned long long m1 =
        (unsigned long long)m1lo | ((unsigned long long)m1hi << 32);

    // ==== fused backward: out = -(W1[0:32,:] @ (mask1 . (W2 @ d2))) ========
    float o[32];
    #pragma unroll
    for (int i = 0; i < 32; i++) o[i] = 0.0f;

    #pragma unroll 2
    for (int k = 0; k < HID; k++) {
        const float4* wp = reinterpret_cast<const float4*>(sW2 + k * 64);
        float s0 = 0.f, s1 = 0.f, s2 = 0.f, s3 = 0.f;
        #pragma unroll
        for (int j4 = 0; j4 < 16; j4++) {
            float4 w = wp[j4];
            s0 = fmaf(w.x, d2[4*j4+0], s0);
            s1 = fmaf(w.y, d2[4*j4+1], s1);
            s2 = fmaf(w.z, d2[4*j4+2], s2);
            s3 = fmaf(w.w, d2[4*j4+3], s3);
        }
        float tk = ((s0 + s1) + (s2 + s3));
        tk = ((m1 >> k) & 1ull) ? -tk : 0.0f;   // negate here: out = -W1.d1

        const float4* vp = reinterpret_cast<const float4*>(sW1T + k * 32);
        #pragma unroll
        for (int i4 = 0; i4 < 8; i4++) {
            float4 w = vp[i4];
            o[4*i4+0] = fmaf(tk, w.x, o[4*i4+0]);
            o[4*i4+1] = fmaf(tk, w.y, o[4*i4+1]);
            o[4*i4+2] = fmaf(tk, w.z, o[4*i4+2]);
            o[4*i4+3] = fmaf(tk, w.w, o[4*i4+3]);
        }
    }

    // ---- vectorized store ----
    float4* og = reinterpret_cast<float4*>(out + (size_t)s * 32);
    #pragma unroll
    for (int i4 = 0; i4 < 8; i4++) {
        float4 r;
        r.x = o[4*i4+0]; r.y = o[4*i4+1]; r.z = o[4*i4+2]; r.w = o[4*i4+3];
        og[i4] = r;
    }
}

extern "C" void kernel_launch(void* const* d_in, const int* in_sizes, int n_in,
                              void* d_out, int out_size)
{
    const float* X  = (const float*)d_in[0];
    const float* W1 = (const float*)d_in[1];
    const float* b1 = (const float*)d_in[2];
    const float* W2 = (const float*)d_in[3];
    const float* b2 = (const float*)d_in[4];
    const float* W3 = (const float*)d_in[5];
    float* out = (float*)d_out;

    const int B = in_sizes[0] / 64;
    const int block = 128;
    const int grid = (B + block - 1) / block;
    const size_t smem_bytes = SMEM_FLOATS * sizeof(float);

    cudaFuncSetAttribute(lnn_kernel,
                         cudaFuncAttributeMaxDynamicSharedMemorySize,
                         (int)smem_bytes);
    lnn_kernel<<<grid, block, smem_bytes>>>(X, W1, b1, W2, b2, W3, out, B);
}

// round 3
// speedup vs baseline: 1.2252x; 1.2252x over previous
#include <cuda_runtime.h>
#include <cuda_bf16.h>

// LNN Euler-Lagrange residual: ReLU MLP => grad-of-grad vanishes, output is
// exactly -dL/dq (one forward for masks + one backward).
//
// Round-3 structure: 2 samples per thread packed into f32x2 lanes
// (Blackwell fma.rn.f32x2 = 2 FMAs/instr on the fma pipe; weight duplication
// movs ride the alu pipe concurrently). Weight LDS broadcast bytes per sample
// are halved. One 64-entry u64 register array, reused (h then t), indexed
// only by compile-time constants.

typedef unsigned long long u64;

__device__ __forceinline__ u64 pack2(float lo, float hi) {
    u64 d; asm("mov.b64 %0, {%1, %2};" : "=l"(d) : "f"(lo), "f"(hi)); return d;
}
__device__ __forceinline__ void unpack2(u64 v, float& lo, float& hi) {
    asm("mov.b64 {%0, %1}, %2;" : "=f"(lo), "=f"(hi) : "l"(v));
}
__device__ __forceinline__ u64 fma2(u64 a, u64 b, u64 c) {
    u64 d; asm("fma.rn.f32x2 %0, %1, %2, %3;" : "=l"(d) : "l"(a), "l"(b), "l"(c)); return d;
}
__device__ __forceinline__ u64 add2(u64 a, u64 b) {
    u64 d; asm("add.rn.f32x2 %0, %1, %2;" : "=l"(d) : "l"(a), "l"(b)); return d;
}

__global__ void __launch_bounds__(128)
lnn_kernel(const float* __restrict__ X,
           const float* __restrict__ W1g, const float* __restrict__ b1g,
           const float* __restrict__ W2g, const float* __restrict__ b2g,
           const float* __restrict__ W3g,
           float* __restrict__ out, int B)
{
    __shared__ float sW1[4096];    // row i: W1[i,:]   (fwd L1; also bwd out dot)
    __shared__ float sW2T[4096];   // row j: W2[:,j]   (L2 sign dot; t-accum)
    __shared__ float sb1[64], sb2[64], sW3[64];

    const int t = threadIdx.x;
    for (int i = t; i < 4096; i += 128) {
        sW1[i] = W1g[i];
        const int r = i >> 6, c = i & 63;
        sW2T[c * 64 + r] = W2g[i];
    }
    if (t < 64) { sb1[t] = b1g[t]; sb2[t] = b2g[t]; sW3[t] = W3g[t]; }
    __syncthreads();

    const int sa = blockIdx.x * 256 + t;       // sample in lo half
    int sb = sa + 128;                         // sample in hi half
    if (sa >= B) return;
    const bool bvalid = (sb < B);
    if (!bvalid) sb = sa;

    // ===================== layer 1: h = relu(x@W1 + b1) =====================
    u64 acc[64];
    #pragma unroll
    for (int j = 0; j < 64; j++) { float b = sb1[j]; acc[j] = pack2(b, b); }

    const float4* xa = reinterpret_cast<const float4*>(X + (size_t)sa * 64);
    const float4* xb = reinterpret_cast<const float4*>(X + (size_t)sb * 64);

    #pragma unroll 1
    for (int i4 = 0; i4 < 16; i4++) {
        const float4 va = xa[i4];
        const float4 vb = xb[i4];
        u64 xp0 = pack2(va.x, vb.x);
        u64 xp1 = pack2(va.y, vb.y);
        u64 xp2 = pack2(va.z, vb.z);
        u64 xp3 = pack2(va.w, vb.w);
        const float4* row = reinterpret_cast<const float4*>(sW1 + i4 * 256);
        #pragma unroll
        for (int e = 0; e < 16; e++) {
            float4 w;
            w = row[e];
            acc[4*e+0] = fma2(xp0, pack2(w.x, w.x), acc[4*e+0]);
            acc[4*e+1] = fma2(xp0, pack2(w.y, w.y), acc[4*e+1]);
            acc[4*e+2] = fma2(xp0, pack2(w.z, w.z), acc[4*e+2]);
            acc[4*e+3] = fma2(xp0, pack2(w.w, w.w), acc[4*e+3]);
            w = row[16 + e];
            acc[4*e+0] = fma2(xp1, pack2(w.x, w.x), acc[4*e+0]);
            acc[4*e+1] = fma2(xp1, pack2(w.y, w.y), acc[4*e+1]);
            acc[4*e+2] = fma2(xp1, pack2(w.z, w.z), acc[4*e+2]);
            acc[4*e+3] = fma2(xp1, pack2(w.w, w.w), acc[4*e+3]);
            w = row[32 + e];
            acc[4*e+0] = fma2(xp2, pack2(w.x, w.x), acc[4*e+0]);
            acc[4*e+1] = fma2(xp2, pack2(w.y, w.y), acc[4*e+1]);
            acc[4*e+2] = fma2(xp2, pack2(w.z, w.z), acc[4*e+2]);
            acc[4*e+3] = fma2(xp2, pack2(w.w, w.w), acc[4*e+3]);
            w = row[48 + e];
            acc[4*e+0] = fma2(xp3, pack2(w.x, w.x), acc[4*e+0]);
            acc[4*e+1] = fma2(xp3, pack2(w.y, w.y), acc[4*e+1]);
            acc[4*e+2] = fma2(xp3, pack2(w.z, w.z), acc[4*e+2]);
            acc[4*e+3] = fma2(xp3, pack2(w.w, w.w), acc[4*e+3]);
        }
    }

    // relu + layer-1 mask bits
    u64 m1a = 0ull, m1b = 0ull;
    #pragma unroll
    for (int j = 0; j < 64; j++) {
        float lo, hi; unpack2(acc[j], lo, hi);
        lo = fmaxf(lo, 0.0f); hi = fmaxf(hi, 0.0f);
        if (lo > 0.0f) m1a |= (1ull << j);
        if (hi > 0.0f) m1b |= (1ull << j);
        acc[j] = pack2(lo, hi);
    }

    // ============ layer 2: only sign(h@W2 + b2) is needed ===================
    u64 m2a = 0ull, m2b = 0ull;
    #pragma unroll 1
    for (int j = 0; j < 64; j++) {
        const float4* row = reinterpret_cast<const float4*>(sW2T + j * 64);
        float b = sb2[j];
        u64 g0 = pack2(b, b), g1 = 0ull, g2 = 0ull, g3 = 0ull;
        #pragma unroll
        for (int e = 0; e < 16; e++) {
            float4 w = row[e];
            g0 = fma2(acc[4*e+0], pack2(w.x, w.x), g0);
            g1 = fma2(acc[4*e+1], pack2(w.y, w.y), g1);
            g2 = fma2(acc[4*e+2], pack2(w.z, w.z), g2);
            g3 = fma2(acc[4*e+3], pack2(w.w, w.w), g3);
        }
        u64 g = add2(add2(g0, g1), add2(g2, g3));
        float ga, gb; unpack2(g, ga, gb);
        if (ga > 0.0f) m2a |= (1ull << j);
        if (gb > 0.0f) m2b |= (1ull << j);
    }

    // ===== t = W2 @ d2, d2 = m2 ? W3 : 0; acc reused as t accumulators =====
    #pragma unroll
    for (int j = 0; j < 64; j++) acc[j] = 0ull;

    #pragma unroll 1
    for (int j = 0; j < 64; j++) {
        const float w3 = sW3[j];
        const float d2a = ((m2a >> j) & 1ull) ? w3 : 0.0f;
        const float d2b = ((m2b >> j) & 1ull) ? w3 : 0.0f;
        const u64 d2 = pack2(d2a, d2b);
        const float4* row = reinterpret_cast<const float4*>(sW2T + j * 64);
        #pragma unroll
        for (int e = 0; e < 16; e++) {
            float4 w = row[e];
            acc[4*e+0] = fma2(d2, pack2(w.x, w.x), acc[4*e+0]);
            acc[4*e+1] = fma2(d2, pack2(w.y, w.y), acc[4*e+1]);
            acc[4*e+2] = fma2(d2, pack2(w.z, w.z), acc[4*e+2]);
            acc[4*e+3] = fma2(d2, pack2(w.w, w.w), acc[4*e+3]);
        }
    }

    // gate by m1 and fold the output negation into t
    #pragma unroll
    for (int k = 0; k < 64; k++) {
        float ta, tb; unpack2(acc[k], ta, tb);
        ta = ((m1a >> k) & 1ull) ? -ta : 0.0f;
        tb = ((m1b >> k) & 1ull) ? -tb : 0.0f;
        acc[k] = pack2(ta, tb);
    }

    // ======= out_i = sum_k W1[i,k] * tgated_k  (i < 32, q rows only) ========
    float* oa = out + (size_t)sa * 32;
    float* ob = out + (size_t)sb * 32;
    #pragma unroll 1
    for (int i = 0; i < 32; i++) {
        const float4* row = reinterpret_cast<const float4*>(sW1 + i * 64);
        u64 s0 = 0ull, s1 = 0ull, s2 = 0ull, s3 = 0ull;
        #pragma unroll
        for (int e = 0; e < 16; e++) {
            float4 w = row[e];
            s0 = fma2(acc[4*e+0], pack2(w.x, w.x), s0);
            s1 = fma2(acc[4*e+1], pack2(w.y, w.y), s1);
            s2 = fma2(acc[4*e+2], pack2(w.z, w.z), s2);
            s3 = fma2(acc[4*e+3], pack2(w.w, w.w), s3);
        }
        u64 s = add2(add2(s0, s1), add2(s2, s3));
        float ra, rb; unpack2(s, ra, rb);
        oa[i] = ra;
        if (bvalid) ob[i] = rb;
    }
}

extern "C" void kernel_launch(void* const* d_in, const int* in_sizes, int n_in,
                              void* d_out, int out_size)
{
    const float* X  = (const float*)d_in[0];
    const float* W1 = (const float*)d_in[1];
    const float* b1 = (const float*)d_in[2];
    const float* W2 = (const float*)d_in[3];
    const float* b2 = (const float*)d_in[4];
    const float* W3 = (const float*)d_in[5];
    float* out = (float*)d_out;

    const int B = in_sizes[0] / 64;
    const int grid = (B + 255) / 256;   // 256 samples per 128-thread block
    lnn_kernel<<<grid, 128>>>(X, W1, b1, W2, b2, W3, out, B);
}